// round 2
// baseline (speedup 1.0000x reference)
#include <cuda_runtime.h>
#include <cstdint>

#define N_USERS 50000
#define N_ITEMS 100000
#define N_NODES 150000
#define NNZ     1000000
#define D       64
#define ND      (N_NODES * D)      /* 9,600,000 */
#define N_HOPS  3

// Scratch (no cudaMalloc allowed): ping-pong aggregation buffers + edge weights.
__device__ float g_agg[2][ND];
__device__ float g_v[NNZ];

// ---------------------------------------------------------------------------
// JAX threefry2x32 (exact replica of jax/_src/prng.py threefry2x32 rounds)
// ---------------------------------------------------------------------------
__host__ __device__ __forceinline__ uint32_t rotl32(uint32_t x, int r) {
    return (x << r) | (x >> (32 - r));
}

__host__ __device__ __forceinline__ void threefry2x32(
    uint32_t k0, uint32_t k1, uint32_t x0, uint32_t x1,
    uint32_t& o0, uint32_t& o1)
{
    uint32_t ks2 = k0 ^ k1 ^ 0x1BD11BDAu;
    x0 += k0; x1 += k1;
#define TF_R4(a,b,c,d)                                   \
    x0 += x1; x1 = rotl32(x1,(a)); x1 ^= x0;             \
    x0 += x1; x1 = rotl32(x1,(b)); x1 ^= x0;             \
    x0 += x1; x1 = rotl32(x1,(c)); x1 ^= x0;             \
    x0 += x1; x1 = rotl32(x1,(d)); x1 ^= x0;
    TF_R4(13,15,26,6);   x0 += k1;  x1 += ks2 + 1u;
    TF_R4(17,29,16,24);  x0 += ks2; x1 += k0  + 2u;
    TF_R4(13,15,26,6);   x0 += k0;  x1 += k1  + 3u;
    TF_R4(17,29,16,24);  x0 += k1;  x1 += ks2 + 4u;
    TF_R4(13,15,26,6);   x0 += ks2; x1 += k0  + 5u;
#undef TF_R4
    o0 = x0; o1 = x1;
}

// Partitionable-mode random bits for 32-bit width at flat index i (hi word = 0):
//   bits(i) = o0 ^ o1 of threefry2x32(key, (0, i))
__device__ __forceinline__ uint32_t tf_bits(uint32_t k0, uint32_t k1, uint32_t i) {
    uint32_t o0, o1;
    threefry2x32(k0, k1, 0u, i, o0, o1);
    return o0 ^ o1;
}

// bits -> uniform in [0,1), exactly as jax.random.uniform for float32
__device__ __forceinline__ float u01(uint32_t bits) {
    return __uint_as_float((bits >> 9) | 0x3F800000u) - 1.0f;
}

// ---------------------------------------------------------------------------
// Kernels
// ---------------------------------------------------------------------------

// out layout: [node, hop(4), d(64)] f32.  agg[0] <- concat(user,item); out[:,0,:] same.
__global__ void k_init(const float4* __restrict__ ue, const float4* __restrict__ ie,
                       float4* __restrict__ out)
{
    int i = blockIdx.x * blockDim.x + threadIdx.x;   // over ND/4
    if (i >= ND / 4) return;
    int node = i >> 4;           // D/4 = 16 float4 per node
    int q    = i & 15;
    float4 v = (node < N_USERS) ? ue[node * 16 + q]
                                : ie[(node - N_USERS) * 16 + q];
    ((float4*)g_agg[0])[i] = v;
    out[(size_t)node * 64 + q] = v;    // hop 0 slice (256 floats/node = 64 float4)
}

// edge dropout weights: keep iff (0.5 + u) >= 1.0, scale x2.  4 edges per thread.
__global__ void k_edge(const float4* __restrict__ vals, uint32_t k0, uint32_t k1)
{
    int t = blockIdx.x * blockDim.x + threadIdx.x;   // over NNZ/4
    if (t >= NNZ / 4) return;
    uint32_t j = (uint32_t)t * 4u;
    float4 v = vals[t];
    uint32_t b0 = tf_bits(k0, k1, j + 0u);
    uint32_t b1 = tf_bits(k0, k1, j + 1u);
    uint32_t b2 = tf_bits(k0, k1, j + 2u);
    uint32_t b3 = tf_bits(k0, k1, j + 3u);
    float4 w;
    w.x = ((0.5f + u01(b0)) >= 1.0f) ? v.x * 2.0f : 0.0f;
    w.y = ((0.5f + u01(b1)) >= 1.0f) ? v.y * 2.0f : 0.0f;
    w.z = ((0.5f + u01(b2)) >= 1.0f) ? v.z * 2.0f : 0.0f;
    w.w = ((0.5f + u01(b3)) >= 1.0f) ? v.w * 2.0f : 0.0f;
    ((float4*)g_v)[t] = w;
}

__global__ void k_zero(int buf)
{
    int i = blockIdx.x * blockDim.x + threadIdx.x;   // over ND/4
    if (i >= ND / 4) return;
    ((float4*)g_agg[buf])[i] = make_float4(0.f, 0.f, 0.f, 0.f);
}

// SpMM scatter: 16 threads per edge, float4 lanes, vector red.add
__global__ void k_spmm(const int* __restrict__ rows, const int* __restrict__ cols,
                       int src, int dst)
{
    unsigned g = blockIdx.x * blockDim.x + threadIdx.x;   // exactly NNZ*16 threads
    int e = g >> 4;
    int t = g & 15;
    float v = g_v[e];
    if (v == 0.0f) return;
    int c = cols[e];
    int r = rows[e];
    const float4 a = ((const float4*)g_agg[src])[c * 16 + t];
    float4* d = ((float4*)g_agg[dst]) + r * 16 + t;
    asm volatile("red.global.add.v4.f32 [%0], {%1, %2, %3, %4};"
                 :: "l"(d), "f"(a.x * v), "f"(a.y * v), "f"(a.z * v), "f"(a.w * v)
                 : "memory");
}

// message dropout (in place on agg[buf]) + emit hop slice into out.
// 4 elements per thread: 4 independent cipher chains give ILP.
__global__ void k_drop(int buf, float4* __restrict__ out, int hop,
                       uint32_t k0, uint32_t k1)
{
    int t = blockIdx.x * blockDim.x + threadIdx.x;   // over ND/4
    if (t >= ND / 4) return;
    uint32_t j = (uint32_t)t * 4u;

    uint32_t b0 = tf_bits(k0, k1, j + 0u);
    uint32_t b1 = tf_bits(k0, k1, j + 1u);
    uint32_t b2 = tf_bits(k0, k1, j + 2u);
    uint32_t b3 = tf_bits(k0, k1, j + 3u);

    float4* agg = (float4*)g_agg[buf];
    float4 a = agg[t];
    float4 r;
    r.x = (u01(b0) < 0.9f) ? a.x * (1.0f / 0.9f) : 0.0f;
    r.y = (u01(b1) < 0.9f) ? a.y * (1.0f / 0.9f) : 0.0f;
    r.z = (u01(b2) < 0.9f) ? a.z * (1.0f / 0.9f) : 0.0f;
    r.w = (u01(b3) < 0.9f) ? a.w * (1.0f / 0.9f) : 0.0f;
    agg[t] = r;

    // out float4 index: node*64 + (hop+1)*16 + (d/4);  d = j & 63, node = j >> 6
    int node = (int)(j >> 6);
    int q    = (int)((j & 63u) >> 2);
    out[(size_t)node * 64 + (size_t)(hop + 1) * 16 + q] = r;
}

// ---------------------------------------------------------------------------
// Launch
// ---------------------------------------------------------------------------
extern "C" void kernel_launch(void* const* d_in, const int* in_sizes, int n_in,
                              void* d_out, int out_size)
{
    const float4* ue   = (const float4*)d_in[0];
    const float4* ie   = (const float4*)d_in[1];
    const int*    rows = (const int*)d_in[2];
    const int*    cols = (const int*)d_in[3];
    const float4* vals = (const float4*)d_in[4];
    float*        out  = (float*)d_out;

    // Host-side key chain, partitionable ("fold-like") split:
    //   split(key, 3)[i] = threefry2x32(key, (0, i))   (full output pair)
    //   key, k_e, k_m = split(key, 3)
    uint32_t key0 = 0u, key1 = 42u;   // jax.random.key(42) -> (0, 42)
    uint32_t ke[N_HOPS][2], km[N_HOPS][2];
    for (int h = 0; h < N_HOPS; h++) {
        uint32_t n0, n1;
        threefry2x32(key0, key1, 0u, 0u, n0, n1);
        threefry2x32(key0, key1, 0u, 1u, ke[h][0], ke[h][1]);
        threefry2x32(key0, key1, 0u, 2u, km[h][0], km[h][1]);
        key0 = n0; key1 = n1;
    }

    const int B = 256;
    k_init<<<(ND / 4 + B - 1) / B, B>>>(ue, ie, (float4*)out);

    int cur = 0;
    for (int h = 0; h < N_HOPS; h++) {
        int nxt = cur ^ 1;
        k_edge<<<(NNZ / 4 + B - 1) / B, B>>>(vals, ke[h][0], ke[h][1]);
        k_zero<<<(ND / 4 + B - 1) / B, B>>>(nxt);
        k_spmm<<<(NNZ * 16) / B, B>>>(rows, cols, cur, nxt);
        k_drop<<<(ND / 4 + B - 1) / B, B>>>(nxt, (float4*)out, h, km[h][0], km[h][1]);
        cur = nxt;
    }
}

// round 3
// speedup vs baseline: 1.4148x; 1.4148x over previous
#include <cuda_runtime.h>
#include <cstdint>

#define N_USERS 50000
#define N_ITEMS 100000
#define N_NODES 150000
#define NNZ     1000000
#define D       64
#define ND      (N_NODES * D)      /* 9,600,000 */
#define N_HOPS  3

// Scratch (no cudaMalloc allowed)
__device__ float g_agg[2][ND];      // ping-pong aggregation buffers
__device__ float g_cv[NNZ];         // compacted kept-edge weights
__device__ int2  g_rc[NNZ];         // compacted kept-edge (row, col)
__device__ int   g_cnt[4];          // per-hop kept-edge counters

// ---------------------------------------------------------------------------
// JAX threefry2x32 (exact replica of jax/_src/prng.py rounds)
// ---------------------------------------------------------------------------
__host__ __device__ __forceinline__ uint32_t rotl32(uint32_t x, int r) {
    return (x << r) | (x >> (32 - r));
}

__host__ __device__ __forceinline__ void threefry2x32(
    uint32_t k0, uint32_t k1, uint32_t x0, uint32_t x1,
    uint32_t& o0, uint32_t& o1)
{
    uint32_t ks2 = k0 ^ k1 ^ 0x1BD11BDAu;
    x0 += k0; x1 += k1;
#define TF_R4(a,b,c,d)                                   \
    x0 += x1; x1 = rotl32(x1,(a)); x1 ^= x0;             \
    x0 += x1; x1 = rotl32(x1,(b)); x1 ^= x0;             \
    x0 += x1; x1 = rotl32(x1,(c)); x1 ^= x0;             \
    x0 += x1; x1 = rotl32(x1,(d)); x1 ^= x0;
    TF_R4(13,15,26,6);   x0 += k1;  x1 += ks2 + 1u;
    TF_R4(17,29,16,24);  x0 += ks2; x1 += k0  + 2u;
    TF_R4(13,15,26,6);   x0 += k0;  x1 += k1  + 3u;
    TF_R4(17,29,16,24);  x0 += k1;  x1 += ks2 + 4u;
    TF_R4(13,15,26,6);   x0 += ks2; x1 += k0  + 5u;
#undef TF_R4
    o0 = x0; o1 = x1;
}

// Partitionable-mode random bits at flat index i: bits = o0 ^ o1 of block (0, i)
__device__ __forceinline__ uint32_t tf_bits(uint32_t k0, uint32_t k1, uint32_t i) {
    uint32_t o0, o1;
    threefry2x32(k0, k1, 0u, i, o0, o1);
    return o0 ^ o1;
}

__device__ __forceinline__ float u01(uint32_t bits) {
    return __uint_as_float((bits >> 9) | 0x3F800000u) - 1.0f;
}

// ---------------------------------------------------------------------------
// Kernels
// ---------------------------------------------------------------------------

// agg[0] <- concat(user,item); out hop-0 slice; zero agg[1]; zero counters.
__global__ void k_init(const float4* __restrict__ ue, const float4* __restrict__ ie,
                       float4* __restrict__ out)
{
    int i = blockIdx.x * blockDim.x + threadIdx.x;   // over ND/4
    if (i >= ND / 4) return;
    int node = i >> 4;           // 16 float4 per node
    int q    = i & 15;
    float4 v = (node < N_USERS) ? ue[node * 16 + q]
                                : ie[(node - N_USERS) * 16 + q];
    ((float4*)g_agg[0])[i] = v;
    ((float4*)g_agg[1])[i] = make_float4(0.f, 0.f, 0.f, 0.f);
    out[(size_t)node * 64 + q] = v;    // 256 floats/node = 64 float4
    if (i < 4) g_cnt[i] = 0;
}

// Edge dropout + compaction. 4 edges/thread, warp-aggregated counter update.
__global__ void k_edge(const float4* __restrict__ vals,
                       const int4*  __restrict__ rows,
                       const int4*  __restrict__ cols,
                       uint32_t k0, uint32_t k1, int hop)
{
    int t    = blockIdx.x * blockDim.x + threadIdx.x;   // over NNZ/4 (guarded)
    int lane = threadIdx.x & 31;
    bool live = (t < NNZ / 4);

    float w[4];
    int   r[4], c[4];
    int   kept = 0;
    unsigned kmask = 0;

    if (live) {
        uint32_t j = (uint32_t)t * 4u;
        float4 v  = vals[t];
        int4   rr = rows[t];
        int4   cc = cols[t];
        float vv[4] = {v.x, v.y, v.z, v.w};
        int    ra[4] = {rr.x, rr.y, rr.z, rr.w};
        int    ca[4] = {cc.x, cc.y, cc.z, cc.w};
#pragma unroll
        for (int i = 0; i < 4; i++) {
            uint32_t b = tf_bits(k0, k1, j + (uint32_t)i);
            if ((0.5f + u01(b)) >= 1.0f) {
                w[kept] = vv[i] * 2.0f;
                r[kept] = ra[i];
                c[kept] = ca[i];
                kept++;
            }
        }
        kmask = kept;  // silence unused warning path
        (void)kmask;
    }

    // warp inclusive scan of kept
    int off = kept;
#pragma unroll
    for (int d = 1; d < 32; d <<= 1) {
        int n = __shfl_up_sync(0xFFFFFFFFu, off, d);
        if (lane >= d) off += n;
    }
    int total = __shfl_sync(0xFFFFFFFFu, off, 31);
    int base  = 0;
    if (lane == 31 && total > 0) base = atomicAdd(&g_cnt[hop], total);
    base = __shfl_sync(0xFFFFFFFFu, base, 31);

    int pos = base + off - kept;
#pragma unroll
    for (int i = 0; i < 4; i++) {
        if (i < kept) {
            g_cv[pos + i] = w[i];
            g_rc[pos + i] = make_int2(r[i], c[i]);
        }
    }
}

// SpMM scatter over the compacted edge list.
// 16 threads per edge-group of 4 edges: batched meta loads -> 4 independent
// gathers -> 4 vector reds (no return latency).  MLP = 4.
__global__ void k_spmm(int src, int dst, int hop)
{
    unsigned g  = blockIdx.x * blockDim.x + threadIdx.x;  // NNZ*4 threads
    int      eg = (int)(g >> 4);
    int      t  = (int)(g & 15);
    int count = g_cnt[hop];
    int base  = eg * 4;
    if (base >= count) return;
    int n = count - base; if (n > 4) n = 4;

    const float4* A = (const float4*)g_agg[src];
    float4*       Dd = (float4*)g_agg[dst];

    float v[4]; int2 rc[4];
#pragma unroll
    for (int i = 0; i < 4; i++)
        if (i < n) { v[i] = g_cv[base + i]; rc[i] = g_rc[base + i]; }

    float4 a[4];
#pragma unroll
    for (int i = 0; i < 4; i++)
        if (i < n) a[i] = A[rc[i].y * 16 + t];

#pragma unroll
    for (int i = 0; i < 4; i++) {
        if (i < n) {
            float4* d = Dd + rc[i].x * 16 + t;
            asm volatile("red.global.add.v4.f32 [%0], {%1, %2, %3, %4};"
                         :: "l"(d), "f"(a[i].x * v[i]), "f"(a[i].y * v[i]),
                            "f"(a[i].z * v[i]), "f"(a[i].w * v[i])
                         : "memory");
        }
    }
}

// Message dropout (in place on agg[buf]) + emit hop slice + zero next dst buffer.
__global__ void k_drop(int buf, int zbuf, float4* __restrict__ out, int hop,
                       uint32_t k0, uint32_t k1)
{
    int t = blockIdx.x * blockDim.x + threadIdx.x;   // over ND/4
    if (t >= ND / 4) return;
    uint32_t j = (uint32_t)t * 4u;

    uint32_t b0 = tf_bits(k0, k1, j + 0u);
    uint32_t b1 = tf_bits(k0, k1, j + 1u);
    uint32_t b2 = tf_bits(k0, k1, j + 2u);
    uint32_t b3 = tf_bits(k0, k1, j + 3u);

    float4* agg = (float4*)g_agg[buf];
    float4 a = agg[t];
    float4 r;
    r.x = (u01(b0) < 0.9f) ? a.x * (1.0f / 0.9f) : 0.0f;
    r.y = (u01(b1) < 0.9f) ? a.y * (1.0f / 0.9f) : 0.0f;
    r.z = (u01(b2) < 0.9f) ? a.z * (1.0f / 0.9f) : 0.0f;
    r.w = (u01(b3) < 0.9f) ? a.w * (1.0f / 0.9f) : 0.0f;
    agg[t] = r;

    if (zbuf >= 0)
        ((float4*)g_agg[zbuf])[t] = make_float4(0.f, 0.f, 0.f, 0.f);

    int node = (int)(j >> 6);
    int q    = (int)((j & 63u) >> 2);
    out[(size_t)node * 64 + (size_t)(hop + 1) * 16 + q] = r;
}

// ---------------------------------------------------------------------------
// Launch
// ---------------------------------------------------------------------------
extern "C" void kernel_launch(void* const* d_in, const int* in_sizes, int n_in,
                              void* d_out, int out_size)
{
    const float4* ue   = (const float4*)d_in[0];
    const float4* ie   = (const float4*)d_in[1];
    const int4*   rows = (const int4*)d_in[2];
    const int4*   cols = (const int4*)d_in[3];
    const float4* vals = (const float4*)d_in[4];
    float*        out  = (float*)d_out;

    // Partitionable ("fold-like") split: split(key,3)[i] = threefry(key, (0,i))
    uint32_t key0 = 0u, key1 = 42u;   // jax.random.key(42)
    uint32_t ke[N_HOPS][2], km[N_HOPS][2];
    for (int h = 0; h < N_HOPS; h++) {
        uint32_t n0, n1;
        threefry2x32(key0, key1, 0u, 0u, n0, n1);
        threefry2x32(key0, key1, 0u, 1u, ke[h][0], ke[h][1]);
        threefry2x32(key0, key1, 0u, 2u, km[h][0], km[h][1]);
        key0 = n0; key1 = n1;
    }

    const int B = 256;
    k_init<<<(ND / 4 + B - 1) / B, B>>>(ue, ie, (float4*)out);

    int cur = 0;
    for (int h = 0; h < N_HOPS; h++) {
        int nxt = cur ^ 1;
        k_edge<<<(NNZ / 4 + B - 1) / B, B>>>(vals, rows, cols, ke[h][0], ke[h][1], h);
        k_spmm<<<(NNZ * 4) / B, B>>>(cur, nxt, h);
        // zero the buffer that becomes dst next hop (skip after last hop)
        int zb = (h + 1 < N_HOPS) ? cur : -1;
        k_drop<<<(ND / 4 + B - 1) / B, B>>>(nxt, zb, (float4*)out, h, km[h][0], km[h][1]);
        cur = nxt;
    }
}

// round 4
// speedup vs baseline: 1.5009x; 1.0608x over previous
#include <cuda_runtime.h>
#include <cstdint>

#define N_USERS 50000
#define N_ITEMS 100000
#define N_NODES 150000
#define NNZ     1000000
#define D       64
#define ND      (N_NODES * D)      /* 9,600,000 */
#define N_HOPS  3

// keep message iff bits < 0xE6666600  (== u01(bits) < 0.9f exactly)
#define MSG_TH  0xE6666600u

// Scratch (no cudaMalloc allowed)
__device__ float g_agg[2][ND];        // ping-pong aggregation buffers
__device__ float g_cv[N_HOPS][NNZ];   // compacted kept-edge weights, per hop
__device__ int2  g_rc[N_HOPS][NNZ];   // compacted kept-edge (row, col), per hop
__device__ int   g_cnt[4];            // per-hop kept-edge counters

// ---------------------------------------------------------------------------
// JAX threefry2x32 (exact replica of jax/_src/prng.py rounds)
// ---------------------------------------------------------------------------
__host__ __device__ __forceinline__ uint32_t rotl32(uint32_t x, int r) {
    return (x << r) | (x >> (32 - r));
}

__host__ __device__ __forceinline__ void threefry2x32(
    uint32_t k0, uint32_t k1, uint32_t x0, uint32_t x1,
    uint32_t& o0, uint32_t& o1)
{
    uint32_t ks2 = k0 ^ k1 ^ 0x1BD11BDAu;
    x0 += k0; x1 += k1;
#define TF_R4(a,b,c,d)                                   \
    x0 += x1; x1 = rotl32(x1,(a)); x1 ^= x0;             \
    x0 += x1; x1 = rotl32(x1,(b)); x1 ^= x0;             \
    x0 += x1; x1 = rotl32(x1,(c)); x1 ^= x0;             \
    x0 += x1; x1 = rotl32(x1,(d)); x1 ^= x0;
    TF_R4(13,15,26,6);   x0 += k1;  x1 += ks2 + 1u;
    TF_R4(17,29,16,24);  x0 += ks2; x1 += k0  + 2u;
    TF_R4(13,15,26,6);   x0 += k0;  x1 += k1  + 3u;
    TF_R4(17,29,16,24);  x0 += k1;  x1 += ks2 + 4u;
    TF_R4(13,15,26,6);   x0 += ks2; x1 += k0  + 5u;
#undef TF_R4
    o0 = x0; o1 = x1;
}

// Partitionable-mode random bits at flat index i: bits = o0 ^ o1 of block (0, i)
__device__ __forceinline__ uint32_t tf_bits(uint32_t k0, uint32_t k1, uint32_t i) {
    uint32_t o0, o1;
    threefry2x32(k0, k1, 0u, i, o0, o1);
    return o0 ^ o1;
}

// ---------------------------------------------------------------------------
// Kernels
// ---------------------------------------------------------------------------

// out hop-0 slice <- concat(user,item); zero agg[0] (hop-0 dst); zero counters.
__global__ void k_init(const float4* __restrict__ ue, const float4* __restrict__ ie,
                       float4* __restrict__ out)
{
    int i = blockIdx.x * blockDim.x + threadIdx.x;   // over ND/4
    if (i >= ND / 4) return;
    int node = i >> 4;           // 16 float4 per node
    int q    = i & 15;
    float4 v = (node < N_USERS) ? ue[node * 16 + q]
                                : ie[(node - N_USERS) * 16 + q];
    ((float4*)g_agg[0])[i] = make_float4(0.f, 0.f, 0.f, 0.f);
    out[(size_t)node * 64 + q] = v;    // 256 floats/node = 64 float4
    if (i < 4) g_cnt[i] = 0;
}

// Edge dropout + compaction for ALL 3 hops in one pass.
// keep iff (0.5 + u) >= 1.0  <=>  u >= 0.5  <=>  bits sign bit set.
__global__ void k_edge3(const float4* __restrict__ vals,
                        const int4*  __restrict__ rows,
                        const int4*  __restrict__ cols,
                        uint32_t ke00, uint32_t ke01,
                        uint32_t ke10, uint32_t ke11,
                        uint32_t ke20, uint32_t ke21)
{
    int t    = blockIdx.x * blockDim.x + threadIdx.x;   // over NNZ/4 (guarded)
    int lane = threadIdx.x & 31;
    bool live = (t < NNZ / 4);

    float4 v  = make_float4(0.f, 0.f, 0.f, 0.f);
    int4   rr = make_int4(0, 0, 0, 0), cc = make_int4(0, 0, 0, 0);
    if (live) { v = vals[t]; rr = rows[t]; cc = cols[t]; }
    float vv[4] = {v.x, v.y, v.z, v.w};
    int   ra[4] = {rr.x, rr.y, rr.z, rr.w};
    int   ca[4] = {cc.x, cc.y, cc.z, cc.w};
    uint32_t j  = (uint32_t)t * 4u;

    uint32_t K0[3] = {ke00, ke10, ke20};
    uint32_t K1[3] = {ke01, ke11, ke21};

#pragma unroll
    for (int h = 0; h < N_HOPS; h++) {
        float w[4]; int r[4], c[4];
        int kept = 0;
        if (live) {
#pragma unroll
            for (int i = 0; i < 4; i++) {
                uint32_t b = tf_bits(K0[h], K1[h], j + (uint32_t)i);
                if ((int)b < 0) {                     // keep
                    w[kept] = vv[i] * 2.0f;
                    r[kept] = ra[i];
                    c[kept] = ca[i];
                    kept++;
                }
            }
        }
        // warp inclusive scan of kept
        int off = kept;
#pragma unroll
        for (int d = 1; d < 32; d <<= 1) {
            int n = __shfl_up_sync(0xFFFFFFFFu, off, d);
            if (lane >= d) off += n;
        }
        int total = __shfl_sync(0xFFFFFFFFu, off, 31);
        int base  = 0;
        if (lane == 31 && total > 0) base = atomicAdd(&g_cnt[h], total);
        base = __shfl_sync(0xFFFFFFFFu, base, 31);

        int pos = base + off - kept;
#pragma unroll
        for (int i = 0; i < 4; i++) {
            if (i < kept) {
                g_cv[h][pos + i] = w[i];
                g_rc[h][pos + i] = make_int2(r[i], c[i]);
            }
        }
    }
}

// SpMM scatter over the compacted edge list.
// 16 threads per group of 4 edges: batched meta loads -> 4 independent
// gathers -> 4 vector reds.  Hop 0 gathers directly from ue/ie.
__global__ void k_spmm(const float4* __restrict__ ue, const float4* __restrict__ ie,
                       int src, int dst, int hop)
{
    unsigned g  = blockIdx.x * blockDim.x + threadIdx.x;  // NNZ*4 threads
    int      eg = (int)(g >> 4);
    int      t  = (int)(g & 15);
    int count = g_cnt[hop];
    int base  = eg * 4;
    if (base >= count) return;
    int n = count - base; if (n > 4) n = 4;

    float v[4]; int2 rc[4];
#pragma unroll
    for (int i = 0; i < 4; i++)
        if (i < n) { v[i] = g_cv[hop][base + i]; rc[i] = g_rc[hop][base + i]; }

    const float4* A = (const float4*)g_agg[src];
    float4 a[4];
#pragma unroll
    for (int i = 0; i < 4; i++) {
        if (i < n) {
            int c = rc[i].y;
            const float4* p;
            if (hop == 0)
                p = (c < N_USERS) ? (ue + (size_t)c * 16)
                                  : (ie + (size_t)(c - N_USERS) * 16);
            else
                p = A + (size_t)c * 16;
            a[i] = p[t];
        }
    }

    float4* Dd = (float4*)g_agg[dst];
#pragma unroll
    for (int i = 0; i < 4; i++) {
        if (i < n) {
            float4* d = Dd + (size_t)rc[i].x * 16 + t;
            asm volatile("red.global.add.v4.f32 [%0], {%1, %2, %3, %4};"
                         :: "l"(d), "f"(a[i].x * v[i]), "f"(a[i].y * v[i]),
                            "f"(a[i].z * v[i]), "f"(a[i].w * v[i])
                         : "memory");
        }
    }
}

// Message dropout + emit hop slice into out.
// 8 elements/thread (8 independent cipher chains).  Integer-domain keep test.
// Optional writeback to agg (skipped on last hop) and fused zeroing of the
// next hop's destination buffer.
__global__ void k_drop(int buf, int zbuf, int writeback,
                       float4* __restrict__ out, int hop,
                       uint32_t k0, uint32_t k1)
{
    int t = blockIdx.x * blockDim.x + threadIdx.x;   // over ND/8
    if (t >= ND / 8) return;
    uint32_t j = (uint32_t)t * 8u;

    uint32_t b[8];
#pragma unroll
    for (int i = 0; i < 8; i++) b[i] = tf_bits(k0, k1, j + (uint32_t)i);

    float4* agg = (float4*)g_agg[buf];
    float4 a0 = agg[2 * t];
    float4 a1 = agg[2 * t + 1];
    const float s = 1.0f / 0.9f;
    float4 r0, r1;
    r0.x = (b[0] < MSG_TH) ? a0.x * s : 0.0f;
    r0.y = (b[1] < MSG_TH) ? a0.y * s : 0.0f;
    r0.z = (b[2] < MSG_TH) ? a0.z * s : 0.0f;
    r0.w = (b[3] < MSG_TH) ? a0.w * s : 0.0f;
    r1.x = (b[4] < MSG_TH) ? a1.x * s : 0.0f;
    r1.y = (b[5] < MSG_TH) ? a1.y * s : 0.0f;
    r1.z = (b[6] < MSG_TH) ? a1.z * s : 0.0f;
    r1.w = (b[7] < MSG_TH) ? a1.w * s : 0.0f;

    if (writeback) {
        agg[2 * t]     = r0;
        agg[2 * t + 1] = r1;
    }
    if (zbuf >= 0) {
        float4 z = make_float4(0.f, 0.f, 0.f, 0.f);
        ((float4*)g_agg[zbuf])[2 * t]     = z;
        ((float4*)g_agg[zbuf])[2 * t + 1] = z;
    }

    int node = (int)(j >> 6);
    int q    = (int)((j & 63u) >> 2);
    size_t o = (size_t)node * 64 + (size_t)(hop + 1) * 16 + q;
    out[o]     = r0;
    out[o + 1] = r1;
}

// ---------------------------------------------------------------------------
// Launch
// ---------------------------------------------------------------------------
extern "C" void kernel_launch(void* const* d_in, const int* in_sizes, int n_in,
                              void* d_out, int out_size)
{
    const float4* ue   = (const float4*)d_in[0];
    const float4* ie   = (const float4*)d_in[1];
    const int4*   rows = (const int4*)d_in[2];
    const int4*   cols = (const int4*)d_in[3];
    const float4* vals = (const float4*)d_in[4];
    float*        out  = (float*)d_out;

    // Partitionable ("fold-like") split: split(key,3)[i] = threefry(key, (0,i))
    uint32_t key0 = 0u, key1 = 42u;   // jax.random.key(42)
    uint32_t ke[N_HOPS][2], km[N_HOPS][2];
    for (int h = 0; h < N_HOPS; h++) {
        uint32_t n0, n1;
        threefry2x32(key0, key1, 0u, 0u, n0, n1);
        threefry2x32(key0, key1, 0u, 1u, ke[h][0], ke[h][1]);
        threefry2x32(key0, key1, 0u, 2u, km[h][0], km[h][1]);
        key0 = n0; key1 = n1;
    }

    const int B = 256;
    k_init<<<(ND / 4 + B - 1) / B, B>>>(ue, ie, (float4*)out);
    k_edge3<<<(NNZ / 4 + B - 1) / B, B>>>(vals, rows, cols,
                                          ke[0][0], ke[0][1],
                                          ke[1][0], ke[1][1],
                                          ke[2][0], ke[2][1]);

    // Buffer plan (replay-safe):
    //  hop0: src=inputs  dst=agg0 (zeroed by init);   drop0 on agg0, zero agg1
    //  hop1: src=agg0    dst=agg1 (zeroed by drop0);  drop1 on agg1, zero agg0
    //  hop2: src=agg1    dst=agg0 (zeroed by drop1);  drop2 on agg0, out only
    int srcs[3] = {0, 0, 1};   // hop0 src ignored (gathers ue/ie)
    int dsts[3] = {0, 1, 0};
    int zbufs[3] = {1, 0, -1};
    for (int h = 0; h < N_HOPS; h++) {
        k_spmm<<<(NNZ * 4) / B, B>>>(ue, ie, srcs[h], dsts[h], h);
        int wb = (h + 1 < N_HOPS) ? 1 : 0;
        k_drop<<<(ND / 8 + B - 1) / B, B>>>(dsts[h], zbufs[h], wb,
                                            (float4*)out, h, km[h][0], km[h][1]);
    }
}

// round 5
// speedup vs baseline: 1.5179x; 1.0113x over previous
#include <cuda_runtime.h>
#include <cstdint>

#define N_USERS 50000
#define N_ITEMS 100000
#define N_NODES 150000
#define NNZ     1000000
#define D       64
#define ND      (N_NODES * D)      /* 9,600,000 */
#define N_HOPS  3

// keep message iff bits < 0xE6666600  (== u01(bits) < 0.9f exactly)
#define MSG_TH  0xE6666600u

#define NB_INIT 9375               /* ND/4/256 exact */
#define NB_EDGE 977                /* ceil(NNZ/4 / 256) */
#define CAP_GROUPS 135168          /* 4-edge groups; cap = 540,672 kept edges */

// Scratch (no cudaMalloc allowed)
__device__ float g_agg[2][ND];        // ping-pong aggregation buffers
__device__ float g_cv[N_HOPS][NNZ];   // compacted kept-edge weights, per hop
__device__ int2  g_rc[N_HOPS][NNZ];   // compacted kept-edge (row, col), per hop
__device__ int   g_cnt[4];            // per-hop kept-edge counters (zeroed by
                                      // module load, then by last k_drop of
                                      // every call -> replay-safe)

// ---------------------------------------------------------------------------
// JAX threefry2x32.  Host version (key derivation) + device version with all
// adds forced onto the fma pipe (IMAD via runtime-opaque multiplier `one`).
// ---------------------------------------------------------------------------
__host__ __forceinline__ uint32_t rotl32h(uint32_t x, int r) {
    return (x << r) | (x >> (32 - r));
}

__host__ void threefry2x32_host(uint32_t k0, uint32_t k1, uint32_t x0, uint32_t x1,
                                uint32_t& o0, uint32_t& o1)
{
    uint32_t ks2 = k0 ^ k1 ^ 0x1BD11BDAu;
    x0 += k0; x1 += k1;
#define TF_R4(a,b,c,d)                                   \
    x0 += x1; x1 = rotl32h(x1,(a)); x1 ^= x0;            \
    x0 += x1; x1 = rotl32h(x1,(b)); x1 ^= x0;            \
    x0 += x1; x1 = rotl32h(x1,(c)); x1 ^= x0;            \
    x0 += x1; x1 = rotl32h(x1,(d)); x1 ^= x0;
    TF_R4(13,15,26,6);   x0 += k1;  x1 += ks2 + 1u;
    TF_R4(17,29,16,24);  x0 += ks2; x1 += k0  + 2u;
    TF_R4(13,15,26,6);   x0 += k0;  x1 += k1  + 3u;
    TF_R4(17,29,16,24);  x0 += k1;  x1 += ks2 + 4u;
    TF_R4(13,15,26,6);   x0 += ks2; x1 += k0  + 5u;
#undef TF_R4
    o0 = x0; o1 = x1;
}

// add on the fma pipe: IMAD d = a*one + b, `one` is 1 at runtime but opaque
// to ptxas, preventing strength reduction back to IADD3 (alu pipe).
__device__ __forceinline__ uint32_t addi(uint32_t a, uint32_t b, uint32_t one) {
    uint32_t d;
    asm("mad.lo.u32 %0, %1, %2, %3;" : "=r"(d) : "r"(a), "r"(one), "r"(b));
    return d;
}

__device__ __forceinline__ uint32_t rotxor(uint32_t x, int r, uint32_t y) {
    return __funnelshift_l(x, x, (unsigned)r) ^ y;
}

__device__ __forceinline__ void tf_round4(uint32_t& x0, uint32_t& x1,
                                          int a, int b, int c, int d,
                                          uint32_t one)
{
    x0 = addi(x0, x1, one); x1 = rotxor(x1, a, x0);
    x0 = addi(x0, x1, one); x1 = rotxor(x1, b, x0);
    x0 = addi(x0, x1, one); x1 = rotxor(x1, c, x0);
    x0 = addi(x0, x1, one); x1 = rotxor(x1, d, x0);
}

// Partitionable-mode random bits at flat index i: block (0, i), bits = o0^o1.
__device__ __forceinline__ uint32_t tf_bits_i(uint32_t k0, uint32_t k1,
                                              uint32_t ks2, uint32_t i,
                                              uint32_t one)
{
    uint32_t x0 = k0;                 // 0 + k0
    uint32_t x1 = addi(i, k1, one);
    tf_round4(x0, x1, 13, 15, 26,  6, one);
    x0 = addi(x0, k1,  one); x1 = addi(x1, ks2 + 1u, one);
    tf_round4(x0, x1, 17, 29, 16, 24, one);
    x0 = addi(x0, ks2, one); x1 = addi(x1, k0  + 2u, one);
    tf_round4(x0, x1, 13, 15, 26,  6, one);
    x0 = addi(x0, k0,  one); x1 = addi(x1, k1  + 3u, one);
    tf_round4(x0, x1, 17, 29, 16, 24, one);
    x0 = addi(x0, k1,  one); x1 = addi(x1, ks2 + 4u, one);
    tf_round4(x0, x1, 13, 15, 26,  6, one);
    x0 = addi(x0, ks2, one); x1 = addi(x1, k0  + 5u, one);
    return x0 ^ x1;
}

// ---------------------------------------------------------------------------
// Kernels
// ---------------------------------------------------------------------------

// Merged: blocks [0, NB_INIT) do init; blocks [NB_INIT, NB_INIT+NB_EDGE) do
// edge dropout + compaction for all 3 hops.  Disjoint state -> no ordering
// dependency between the two halves.  g_cnt is already 0 at entry (module
// load / previous call's last k_drop).
__global__ void k_init_edge(const float4* __restrict__ ue,
                            const float4* __restrict__ ie,
                            float4* __restrict__ out,
                            const float4* __restrict__ vals,
                            const int4*  __restrict__ rows,
                            const int4*  __restrict__ cols,
                            uint32_t ke00, uint32_t ke01,
                            uint32_t ke10, uint32_t ke11,
                            uint32_t ke20, uint32_t ke21,
                            uint32_t one)
{
    int blk = blockIdx.x;
    if (blk < NB_INIT) {
        // ---- init: out hop-0 slice; zero agg[0] (hop-0 dst) ----
        int i = blk * blockDim.x + threadIdx.x;   // over ND/4, exact
        int node = i >> 4;           // 16 float4 per node
        int q    = i & 15;
        float4 v = (node < N_USERS) ? ue[node * 16 + q]
                                    : ie[(node - N_USERS) * 16 + q];
        ((float4*)g_agg[0])[i] = make_float4(0.f, 0.f, 0.f, 0.f);
        out[(size_t)node * 64 + q] = v;    // 256 floats/node = 64 float4
        return;
    }

    // ---- edge dropout + compaction, 4 edges/thread, all 3 hops ----
    int t    = (blk - NB_INIT) * blockDim.x + threadIdx.x;   // over NNZ/4
    int lane = threadIdx.x & 31;
    bool live = (t < NNZ / 4);

    float4 v  = make_float4(0.f, 0.f, 0.f, 0.f);
    int4   rr = make_int4(0, 0, 0, 0), cc = make_int4(0, 0, 0, 0);
    if (live) { v = vals[t]; rr = rows[t]; cc = cols[t]; }
    float vv[4] = {v.x, v.y, v.z, v.w};
    int   ra[4] = {rr.x, rr.y, rr.z, rr.w};
    int   ca[4] = {cc.x, cc.y, cc.z, cc.w};
    uint32_t j  = (uint32_t)t * 4u;

    uint32_t K0[3] = {ke00, ke10, ke20};
    uint32_t K1[3] = {ke01, ke11, ke21};

#pragma unroll
    for (int h = 0; h < N_HOPS; h++) {
        uint32_t ks2 = K0[h] ^ K1[h] ^ 0x1BD11BDAu;
        float w[4]; int r[4], c[4];
        int kept = 0;
        if (live) {
#pragma unroll
            for (int i = 0; i < 4; i++) {
                uint32_t b = tf_bits_i(K0[h], K1[h], ks2, j + (uint32_t)i, one);
                if ((int)b < 0) {                     // keep: u >= 0.5
                    w[kept] = vv[i] * 2.0f;
                    r[kept] = ra[i];
                    c[kept] = ca[i];
                    kept++;
                }
            }
        }
        // warp inclusive scan of kept
        int off = kept;
#pragma unroll
        for (int d = 1; d < 32; d <<= 1) {
            int n = __shfl_up_sync(0xFFFFFFFFu, off, d);
            if (lane >= d) off += n;
        }
        int total = __shfl_sync(0xFFFFFFFFu, off, 31);
        int base  = 0;
        if (lane == 31 && total > 0) base = atomicAdd(&g_cnt[h], total);
        base = __shfl_sync(0xFFFFFFFFu, base, 31);

        int pos = base + off - kept;
#pragma unroll
        for (int i = 0; i < 4; i++) {
            if (i < kept) {
                g_cv[h][pos + i] = w[i];
                g_rc[h][pos + i] = make_int2(r[i], c[i]);
            }
        }
    }
}

// SpMM scatter over the compacted edge list.
// 16 threads per group of 4 edges: batched meta loads -> 4 independent
// gathers -> 4 vector reds.  Hop 0 gathers directly from ue/ie.
__global__ void k_spmm(const float4* __restrict__ ue, const float4* __restrict__ ie,
                       int src, int dst, int hop)
{
    unsigned g  = blockIdx.x * blockDim.x + threadIdx.x;
    int      eg = (int)(g >> 4);
    int      t  = (int)(g & 15);
    int count = g_cnt[hop];
    int base  = eg * 4;
    if (base >= count) return;
    int n = count - base; if (n > 4) n = 4;

    float v[4]; int2 rc[4];
#pragma unroll
    for (int i = 0; i < 4; i++)
        if (i < n) { v[i] = g_cv[hop][base + i]; rc[i] = g_rc[hop][base + i]; }

    const float4* A = (const float4*)g_agg[src];
    float4 a[4];
#pragma unroll
    for (int i = 0; i < 4; i++) {
        if (i < n) {
            int c = rc[i].y;
            const float4* p;
            if (hop == 0)
                p = (c < N_USERS) ? (ue + (size_t)c * 16)
                                  : (ie + (size_t)(c - N_USERS) * 16);
            else
                p = A + (size_t)c * 16;
            a[i] = p[t];
        }
    }

    float4* Dd = (float4*)g_agg[dst];
#pragma unroll
    for (int i = 0; i < 4; i++) {
        if (i < n) {
            float4* d = Dd + (size_t)rc[i].x * 16 + t;
            asm volatile("red.global.add.v4.f32 [%0], {%1, %2, %3, %4};"
                         :: "l"(d), "f"(a[i].x * v[i]), "f"(a[i].y * v[i]),
                            "f"(a[i].z * v[i]), "f"(a[i].w * v[i])
                         : "memory");
        }
    }
}

// Message dropout + emit hop slice into out.  8 elements/thread.
// Optional agg writeback (skipped on last hop), fused zeroing of the next
// hop's destination buffer, and (last hop only) counter reset for the next
// graph replay.
__global__ void k_drop(int buf, int zbuf, int writeback, int clear_cnt,
                       float4* __restrict__ out, int hop,
                       uint32_t k0, uint32_t k1, uint32_t one)
{
    int t = blockIdx.x * blockDim.x + threadIdx.x;   // over ND/8
    if (t >= ND / 8) return;
    if (clear_cnt && t < 4) g_cnt[t] = 0;   // for next call/replay

    uint32_t ks2 = k0 ^ k1 ^ 0x1BD11BDAu;
    uint32_t j = (uint32_t)t * 8u;

    uint32_t b[8];
#pragma unroll
    for (int i = 0; i < 8; i++) b[i] = tf_bits_i(k0, k1, ks2, j + (uint32_t)i, one);

    float4* agg = (float4*)g_agg[buf];
    float4 a0 = agg[2 * t];
    float4 a1 = agg[2 * t + 1];
    const float s = 1.0f / 0.9f;
    float4 r0, r1;
    r0.x = (b[0] < MSG_TH) ? a0.x * s : 0.0f;
    r0.y = (b[1] < MSG_TH) ? a0.y * s : 0.0f;
    r0.z = (b[2] < MSG_TH) ? a0.z * s : 0.0f;
    r0.w = (b[3] < MSG_TH) ? a0.w * s : 0.0f;
    r1.x = (b[4] < MSG_TH) ? a1.x * s : 0.0f;
    r1.y = (b[5] < MSG_TH) ? a1.y * s : 0.0f;
    r1.z = (b[6] < MSG_TH) ? a1.z * s : 0.0f;
    r1.w = (b[7] < MSG_TH) ? a1.w * s : 0.0f;

    if (writeback) {
        agg[2 * t]     = r0;
        agg[2 * t + 1] = r1;
    }
    if (zbuf >= 0) {
        float4 z = make_float4(0.f, 0.f, 0.f, 0.f);
        ((float4*)g_agg[zbuf])[2 * t]     = z;
        ((float4*)g_agg[zbuf])[2 * t + 1] = z;
    }

    int node = (int)(j >> 6);
    int q    = (int)((j & 63u) >> 2);
    size_t o = (size_t)node * 64 + (size_t)(hop + 1) * 16 + q;
    out[o]     = r0;
    out[o + 1] = r1;
}

// ---------------------------------------------------------------------------
// Launch
// ---------------------------------------------------------------------------
extern "C" void kernel_launch(void* const* d_in, const int* in_sizes, int n_in,
                              void* d_out, int out_size)
{
    const float4* ue   = (const float4*)d_in[0];
    const float4* ie   = (const float4*)d_in[1];
    const int4*   rows = (const int4*)d_in[2];
    const int4*   cols = (const int4*)d_in[3];
    const float4* vals = (const float4*)d_in[4];
    float*        out  = (float*)d_out;

    // Partitionable ("fold-like") split: split(key,3)[i] = threefry(key, (0,i))
    uint32_t key0 = 0u, key1 = 42u;   // jax.random.key(42)
    uint32_t ke[N_HOPS][2], km[N_HOPS][2];
    for (int h = 0; h < N_HOPS; h++) {
        uint32_t n0, n1;
        threefry2x32_host(key0, key1, 0u, 0u, n0, n1);
        threefry2x32_host(key0, key1, 0u, 1u, ke[h][0], ke[h][1]);
        threefry2x32_host(key0, key1, 0u, 2u, km[h][0], km[h][1]);
        key0 = n0; key1 = n1;
    }

    const int B = 256;
    const uint32_t one = 1u;   // runtime-opaque multiplier for IMAD adds

    k_init_edge<<<NB_INIT + NB_EDGE, B>>>(ue, ie, (float4*)out,
                                          vals, rows, cols,
                                          ke[0][0], ke[0][1],
                                          ke[1][0], ke[1][1],
                                          ke[2][0], ke[2][1], one);

    // Buffer plan (replay-safe):
    //  hop0: src=inputs  dst=agg0 (zeroed by init);   drop0 on agg0, zero agg1
    //  hop1: src=agg0    dst=agg1 (zeroed by drop0);  drop1 on agg1, zero agg0
    //  hop2: src=agg1    dst=agg0 (zeroed by drop1);  drop2 out-only, clears cnt
    int srcs[3]  = {0, 0, 1};   // hop0 src ignored (gathers ue/ie)
    int dsts[3]  = {0, 1, 0};
    int zbufs[3] = {1, 0, -1};
    for (int h = 0; h < N_HOPS; h++) {
        k_spmm<<<(CAP_GROUPS * 16) / B, B>>>(ue, ie, srcs[h], dsts[h], h);
        int wb = (h + 1 < N_HOPS) ? 1 : 0;
        int cc = (h + 1 == N_HOPS) ? 1 : 0;
        k_drop<<<(ND / 8 + B - 1) / B, B>>>(dsts[h], zbufs[h], wb, cc,
                                            (float4*)out, h, km[h][0], km[h][1], one);
    }
}